// round 15
// baseline (speedup 1.0000x reference)
#include <cuda_runtime.h>
#include <cuda_fp16.h>
#include <cuda_bf16.h>
#include <mma.h>

using namespace nvcuda;

#define NN      100000
#define INC     512
#define HID     256
#define OUTC    128
#define EMAX    1600000
#define KSTEPS  10
#define ALPHA_F 0.1f
#define ONEMA_F 0.9f
#define LNEPS   1e-5f

// ---------------- static device scratch (no allocation allowed) ----------------
__device__ float  g_h1[(size_t)NN * HID];
__device__ float  g_h2[(size_t)NN * HID];
__device__ float  g_h0[(size_t)NN * OUTC];      // fp32 teleport source
__device__ __half g_h016[(size_t)NN * OUTC];    // fp16 copy of h0
__device__ __half g_cA[(size_t)NN * OUTC];      // fp16 carry ping
__device__ __half g_cB[(size_t)NN * OUTC];      // fp16 carry pong
__device__ float  g_dis[NN];
__device__ int    g_cnt[NN];
__device__ int    g_fill[NN];
__device__ int    g_rowptr[NN + 1];
__device__ int2   g_csr[EMAX];                  // packed {src, weight-bits}
__device__ int    g_bsum[512];

// ---------------- split-bf16 tensor-core GEMM with reg-prefetch ----------------
// C[M,N] = A[M,K]@B[K,N] + bias, fp32 in/out.
// A,B split into bf16 hi/lo per k-chunk; C = Ah*Bh + Ah*Bl + Al*Bh (fp32 accum).
// 128x128 block tile, 256 threads = 8 warps in 2(m) x 4(n); warp tile 64x32.
#define LDA 40     // bf16 elems; 80 B row stride
#define LDB 136    // bf16 elems; 272 B row stride

__global__ void __launch_bounds__(256, 2)
wgemm_bias(const float* __restrict__ A, const float* __restrict__ B,
           const float* __restrict__ bias, float* __restrict__ C,
           int M, int K, int N)
{
    __shared__ __nv_bfloat16 sAh[128 * LDA];
    __shared__ __nv_bfloat16 sAl[128 * LDA];
    __shared__ __nv_bfloat16 sBh[16 * LDB];
    __shared__ __nv_bfloat16 sBl[16 * LDB];
    __shared__ float         sCb[16 * 128];    // replicated bias tile

    const int tid = threadIdx.x;
    const int bm  = blockIdx.y * 128;
    const int bn  = blockIdx.x * 128;
    const int wid = tid >> 5;
    const int wm  = wid >> 2;        // 0..1
    const int wn  = wid & 3;         // 0..3

    for (int i = tid; i < 16 * 128; i += 256)
        sCb[i] = bias[bn + (i & 127)];
    __syncthreads();

    wmma::fragment<wmma::accumulator, 16, 16, 16, float> cf[4][2];
    #pragma unroll
    for (int mf = 0; mf < 4; mf++)
        #pragma unroll
        for (int nf = 0; nf < 2; nf++)
            wmma::load_matrix_sync(cf[mf][nf], sCb + wn * 32 + nf * 16, 128,
                                   wmma::mem_row_major);

    const int a_row = tid >> 1;              // 0..127
    const int a_c4  = (tid & 1) * 8;         // 0 or 8
    const int b_row = tid >> 4;              // 0..15
    const int b_c4  = (tid & 15) * 8;        // 0..120
    const bool m_ok = (bm + a_row) < M;

    const float* a_base = A + (size_t)(bm + a_row) * K + a_c4;
    const float* b_base = B + (size_t)b_row * N + bn + b_c4;

    float va[8], vb[8];
    // prologue: load chunk 0
    {
        float4 v0, v1;
        if (m_ok) { v0 = *(const float4*)a_base; v1 = *(const float4*)(a_base + 4); }
        else      { v0 = make_float4(0,0,0,0); v1 = v0; }
        va[0]=v0.x; va[1]=v0.y; va[2]=v0.z; va[3]=v0.w;
        va[4]=v1.x; va[5]=v1.y; va[6]=v1.z; va[7]=v1.w;
        float4 w0 = *(const float4*)b_base;
        float4 w1 = *(const float4*)(b_base + 4);
        vb[0]=w0.x; vb[1]=w0.y; vb[2]=w0.z; vb[3]=w0.w;
        vb[4]=w1.x; vb[5]=w1.y; vb[6]=w1.z; vb[7]=w1.w;
    }

    const int nt = K / 16;
    for (int t = 0; t < nt; t++) {
        // ---- stage current regs -> smem (hi/lo split) ----
        #pragma unroll
        for (int i = 0; i < 8; i++) {
            __nv_bfloat16 h = __float2bfloat16_rn(va[i]);
            __nv_bfloat16 l = __float2bfloat16_rn(va[i] - __bfloat162float(h));
            sAh[a_row * LDA + a_c4 + i] = h;
            sAl[a_row * LDA + a_c4 + i] = l;
        }
        #pragma unroll
        for (int i = 0; i < 8; i++) {
            __nv_bfloat16 h = __float2bfloat16_rn(vb[i]);
            __nv_bfloat16 l = __float2bfloat16_rn(vb[i] - __bfloat162float(h));
            sBh[b_row * LDB + b_c4 + i] = h;
            sBl[b_row * LDB + b_c4 + i] = l;
        }
        __syncthreads();

        // ---- prefetch next chunk while mma runs ----
        if (t + 1 < nt) {
            const float* ap = a_base + (t + 1) * 16;
            float4 v0, v1;
            if (m_ok) { v0 = *(const float4*)ap; v1 = *(const float4*)(ap + 4); }
            else      { v0 = make_float4(0,0,0,0); v1 = v0; }
            va[0]=v0.x; va[1]=v0.y; va[2]=v0.z; va[3]=v0.w;
            va[4]=v1.x; va[5]=v1.y; va[6]=v1.z; va[7]=v1.w;
            const float* bp = b_base + (size_t)(t + 1) * 16 * N;
            float4 w0 = *(const float4*)bp;
            float4 w1 = *(const float4*)(bp + 4);
            vb[0]=w0.x; vb[1]=w0.y; vb[2]=w0.z; vb[3]=w0.w;
            vb[4]=w1.x; vb[5]=w1.y; vb[6]=w1.z; vb[7]=w1.w;
        }

        // ---- warp-level mma: acc += Ah*Bh + Ah*Bl + Al*Bh ----
        wmma::fragment<wmma::matrix_a, 16, 16, 16, __nv_bfloat16, wmma::row_major> af[4];
        wmma::fragment<wmma::matrix_b, 16, 16, 16, __nv_bfloat16, wmma::row_major> bh[2], bl[2];

        #pragma unroll
        for (int nf = 0; nf < 2; nf++) {
            wmma::load_matrix_sync(bh[nf], sBh + wn * 32 + nf * 16, LDB);
            wmma::load_matrix_sync(bl[nf], sBl + wn * 32 + nf * 16, LDB);
        }
        #pragma unroll
        for (int mf = 0; mf < 4; mf++)
            wmma::load_matrix_sync(af[mf], sAh + (wm * 64 + mf * 16) * LDA, LDA);
        #pragma unroll
        for (int mf = 0; mf < 4; mf++)
            #pragma unroll
            for (int nf = 0; nf < 2; nf++) {
                wmma::mma_sync(cf[mf][nf], af[mf], bh[nf], cf[mf][nf]);
                wmma::mma_sync(cf[mf][nf], af[mf], bl[nf], cf[mf][nf]);
            }
        #pragma unroll
        for (int mf = 0; mf < 4; mf++)
            wmma::load_matrix_sync(af[mf], sAl + (wm * 64 + mf * 16) * LDA, LDA);
        #pragma unroll
        for (int mf = 0; mf < 4; mf++)
            #pragma unroll
            for (int nf = 0; nf < 2; nf++)
                wmma::mma_sync(cf[mf][nf], af[mf], bh[nf], cf[mf][nf]);
        __syncthreads();
    }

    #pragma unroll
    for (int mf = 0; mf < 4; mf++) {
        int m = bm + wm * 64 + mf * 16;
        if (m < M) {
            #pragma unroll
            for (int nf = 0; nf < 2; nf++)
                wmma::store_matrix_sync(C + (size_t)m * N + bn + wn * 32 + nf * 16,
                                        cf[mf][nf], N, wmma::mem_row_major);
        }
    }
}

// ---------------- fused LayerNorm + ReLU (warp per row of 256) ------------------
__global__ void ln_relu_kernel(float* __restrict__ h, const float* __restrict__ g,
                               const float* __restrict__ be, int M)
{
    int warp = (blockIdx.x * blockDim.x + threadIdx.x) >> 5;
    if (warp >= M) return;
    int lane = threadIdx.x & 31;

    float4* row = (float4*)(h + (size_t)warp * HID);
    float4 v0 = row[lane];
    float4 v1 = row[lane + 32];

    float s  = v0.x + v0.y + v0.z + v0.w + v1.x + v1.y + v1.z + v1.w;
    float sq = v0.x * v0.x + v0.y * v0.y + v0.z * v0.z + v0.w * v0.w
             + v1.x * v1.x + v1.y * v1.y + v1.z * v1.z + v1.w * v1.w;
    #pragma unroll
    for (int o = 16; o > 0; o >>= 1) {
        s  += __shfl_xor_sync(0xffffffffu, s, o);
        sq += __shfl_xor_sync(0xffffffffu, sq, o);
    }
    float mu   = s * (1.0f / 256.0f);
    float var  = sq * (1.0f / 256.0f) - mu * mu;
    float rstd = rsqrtf(var + LNEPS);

    const float4* g4 = (const float4*)g;
    const float4* b4 = (const float4*)be;
    float4 G0 = g4[lane], G1 = g4[lane + 32];
    float4 B0 = b4[lane], B1 = b4[lane + 32];

    v0.x = fmaxf((v0.x - mu) * rstd * G0.x + B0.x, 0.f);
    v0.y = fmaxf((v0.y - mu) * rstd * G0.y + B0.y, 0.f);
    v0.z = fmaxf((v0.z - mu) * rstd * G0.z + B0.z, 0.f);
    v0.w = fmaxf((v0.w - mu) * rstd * G0.w + B0.w, 0.f);
    v1.x = fmaxf((v1.x - mu) * rstd * G1.x + B1.x, 0.f);
    v1.y = fmaxf((v1.y - mu) * rstd * G1.y + B1.y, 0.f);
    v1.z = fmaxf((v1.z - mu) * rstd * G1.z + B1.z, 0.f);
    v1.w = fmaxf((v1.w - mu) * rstd * G1.w + B1.w, 0.f);

    row[lane]      = v0;
    row[lane + 32] = v1;
}

// ---------------- graph prep: CSR by dst ---------------------------------------
__global__ void zero_kernel(int* __restrict__ cnt, int* __restrict__ fill)
{
    int i = blockIdx.x * blockDim.x + threadIdx.x;
    if (i < NN) { cnt[i] = 0; fill[i] = 0; }
}

__global__ void deg_count_kernel(const int* __restrict__ dst, int* __restrict__ cnt, int E)
{
    int e = blockIdx.x * blockDim.x + threadIdx.x;
    if (e < E) atomicAdd(&cnt[dst[e]], 1);
}

__global__ void dis_kernel(const int* __restrict__ cnt, float* __restrict__ dis)
{
    int i = blockIdx.x * blockDim.x + threadIdx.x;
    if (i < NN) dis[i] = rsqrtf((float)(cnt[i] + 1));
}

__global__ void scan_partial(const int* __restrict__ cnt, int* __restrict__ rowptr,
                             int* __restrict__ bsum)
{
    __shared__ int s[256];
    int tid = threadIdx.x;
    int i = blockIdx.x * 256 + tid;
    int v = (i < NN) ? cnt[i] : 0;
    s[tid] = v;
    __syncthreads();
    #pragma unroll
    for (int o = 1; o < 256; o <<= 1) {
        int t = 0;
        if (tid >= o) t = s[tid - o];
        __syncthreads();
        if (tid >= o) s[tid] += t;
        __syncthreads();
    }
    if (i < NN) rowptr[i] = s[tid] - v;
    if (tid == 255) bsum[blockIdx.x] = s[255];
}

__global__ void scan_bsums(int* __restrict__ bsum, int nb)
{
    __shared__ int s[512];
    int tid = threadIdx.x;
    int v = (tid < nb) ? bsum[tid] : 0;
    s[tid] = v;
    __syncthreads();
    #pragma unroll
    for (int o = 1; o < 512; o <<= 1) {
        int t = 0;
        if (tid >= o) t = s[tid - o];
        __syncthreads();
        if (tid >= o) s[tid] += t;
        __syncthreads();
    }
    if (tid < nb) bsum[tid] = s[tid] - v;
}

__global__ void add_offsets(int* __restrict__ rowptr, const int* __restrict__ bsum, int E)
{
    int i = blockIdx.x * blockDim.x + threadIdx.x;
    if (i < NN) rowptr[i] += bsum[i >> 8];
    if (i == 0) rowptr[NN] = E;
}

__global__ void fill_kernel(const int* __restrict__ src, const int* __restrict__ dst,
                            const float* __restrict__ dis,
                            const int* __restrict__ rowptr, int* __restrict__ fill,
                            int2* __restrict__ csr, int E)
{
    int e = blockIdx.x * blockDim.x + threadIdx.x;
    if (e >= E) return;
    int si = src[e];
    int di = dst[e];
    int p = rowptr[di] + atomicAdd(&fill[di], 1);
    float w = ONEMA_F * dis[si] * dis[di];
    csr[p] = make_int2(si, __float_as_int(w));
}

// ---------------- fp32 -> fp16 convert (4 elems / thread) ----------------------
__global__ void f2h_kernel(const float* __restrict__ in, __half* __restrict__ out)
{
    int idx = blockIdx.x * blockDim.x + threadIdx.x;   // over NN*32 float4s
    if (idx >= NN * (OUTC / 4)) return;
    float4 v = ((const float4*)in)[idx];
    __half2 lo = __floats2half2_rn(v.x, v.y);
    __half2 hi = __floats2half2_rn(v.z, v.w);
    uint2 o;
    o.x = *(unsigned*)&lo;
    o.y = *(unsigned*)&hi;
    ((uint2*)out)[idx] = o;
}

// ---------------- APPNP step: 2 nodes per warp, 8-deep gather pipeline ----------
__device__ __forceinline__ void acc_row(float* acc, const uint4& p, float w)
{
    float2 a0 = __half22float2(*(__half2*)&p.x);
    float2 a1 = __half22float2(*(__half2*)&p.y);
    float2 a2 = __half22float2(*(__half2*)&p.z);
    float2 a3 = __half22float2(*(__half2*)&p.w);
    acc[0] = fmaf(w, a0.x, acc[0]); acc[1] = fmaf(w, a0.y, acc[1]);
    acc[2] = fmaf(w, a1.x, acc[2]); acc[3] = fmaf(w, a1.y, acc[3]);
    acc[4] = fmaf(w, a2.x, acc[4]); acc[5] = fmaf(w, a2.y, acc[5]);
    acc[6] = fmaf(w, a3.x, acc[6]); acc[7] = fmaf(w, a3.y, acc[7]);
}

__global__ void __launch_bounds__(256)
appnp_step_kernel(const int* __restrict__ rowptr,
                  const int2* __restrict__ csr,
                  const float* __restrict__ dis,
                  const float* __restrict__ h0f,
                  const __half* __restrict__ h016,
                  const __half* __restrict__ carry,
                  __half* __restrict__ out16,
                  float* __restrict__ outf,
                  int last)
{
    int warp_id = (blockIdx.x * blockDim.x + threadIdx.x) >> 5;
    int lane = threadIdx.x & 31;
    int node = warp_id * 2 + (lane >> 4);
    int l16  = lane & 15;
    if (node >= NN) return;

    const uint4* c = (const uint4*)carry;
    int beg = rowptr[node];
    int end = rowptr[node + 1];
    float ds = dis[node];
    float wself = ONEMA_F * ds * ds;

    uint4 cv = c[node * 16 + l16];
    float acc[8];
    {
        float2 s0 = __half22float2(*(__half2*)&cv.x);
        float2 s1 = __half22float2(*(__half2*)&cv.y);
        float2 s2 = __half22float2(*(__half2*)&cv.z);
        float2 s3 = __half22float2(*(__half2*)&cv.w);
        acc[0] = wself * s0.x; acc[1] = wself * s0.y;
        acc[2] = wself * s1.x; acc[3] = wself * s1.y;
        acc[4] = wself * s2.x; acc[5] = wself * s2.y;
        acc[6] = wself * s3.x; acc[7] = wself * s3.y;
    }

    int e = beg;
    // 8-deep: all 8 csr entries, then all 8 row gathers in flight, then FMAs
    for (; e + 7 < end; e += 8) {
        int2 c0 = __ldg(&csr[e]);
        int2 c1 = __ldg(&csr[e + 1]);
        int2 c2 = __ldg(&csr[e + 2]);
        int2 c3 = __ldg(&csr[e + 3]);
        int2 c4 = __ldg(&csr[e + 4]);
        int2 c5 = __ldg(&csr[e + 5]);
        int2 c6 = __ldg(&csr[e + 6]);
        int2 c7 = __ldg(&csr[e + 7]);
        uint4 p0 = c[c0.x * 16 + l16];
        uint4 p1 = c[c1.x * 16 + l16];
        uint4 p2 = c[c2.x * 16 + l16];
        uint4 p3 = c[c3.x * 16 + l16];
        uint4 p4 = c[c4.x * 16 + l16];
        uint4 p5 = c[c5.x * 16 + l16];
        uint4 p6 = c[c6.x * 16 + l16];
        uint4 p7 = c[c7.x * 16 + l16];
        acc_row(acc, p0, __int_as_float(c0.y));
        acc_row(acc, p1, __int_as_float(c1.y));
        acc_row(acc, p2, __int_as_float(c2.y));
        acc_row(acc, p3, __int_as_float(c3.y));
        acc_row(acc, p4, __int_as_float(c4.y));
        acc_row(acc, p5, __int_as_float(c5.y));
        acc_row(acc, p6, __int_as_float(c6.y));
        acc_row(acc, p7, __int_as_float(c7.y));
    }
    for (; e + 3 < end; e += 4) {
        int2 c0 = __ldg(&csr[e]);
        int2 c1 = __ldg(&csr[e + 1]);
        int2 c2 = __ldg(&csr[e + 2]);
        int2 c3 = __ldg(&csr[e + 3]);
        uint4 p0 = c[c0.x * 16 + l16];
        uint4 p1 = c[c1.x * 16 + l16];
        uint4 p2 = c[c2.x * 16 + l16];
        uint4 p3 = c[c3.x * 16 + l16];
        acc_row(acc, p0, __int_as_float(c0.y));
        acc_row(acc, p1, __int_as_float(c1.y));
        acc_row(acc, p2, __int_as_float(c2.y));
        acc_row(acc, p3, __int_as_float(c3.y));
    }
    for (; e < end; e++) {
        int2 c0 = __ldg(&csr[e]);
        uint4 p0 = c[c0.x * 16 + l16];
        acc_row(acc, p0, __int_as_float(c0.y));
    }

    if (last) {
        const float4* h4 = (const float4*)h0f + node * 32 + l16 * 2;
        float4 ha = __ldcs(h4);
        float4 hb = __ldcs(h4 + 1);
        float4 oa, ob;
        oa.x = fmaf(ALPHA_F, ha.x, acc[0]);
        oa.y = fmaf(ALPHA_F, ha.y, acc[1]);
        oa.z = fmaf(ALPHA_F, ha.z, acc[2]);
        oa.w = fmaf(ALPHA_F, ha.w, acc[3]);
        ob.x = fmaf(ALPHA_F, hb.x, acc[4]);
        ob.y = fmaf(ALPHA_F, hb.y, acc[5]);
        ob.z = fmaf(ALPHA_F, hb.z, acc[6]);
        ob.w = fmaf(ALPHA_F, hb.w, acc[7]);
        float4* o4 = (float4*)outf + node * 32 + l16 * 2;
        __stcs(o4, oa);
        __stcs(o4 + 1, ob);
    } else {
        uint4 hp = ((const uint4*)h016)[node * 16 + l16];
        float2 h0v = __half22float2(*(__half2*)&hp.x);
        float2 h1v = __half22float2(*(__half2*)&hp.y);
        float2 h2v = __half22float2(*(__half2*)&hp.z);
        float2 h3v = __half22float2(*(__half2*)&hp.w);
        __half2 q0 = __floats2half2_rn(fmaf(ALPHA_F, h0v.x, acc[0]),
                                       fmaf(ALPHA_F, h0v.y, acc[1]));
        __half2 q1 = __floats2half2_rn(fmaf(ALPHA_F, h1v.x, acc[2]),
                                       fmaf(ALPHA_F, h1v.y, acc[3]));
        __half2 q2 = __floats2half2_rn(fmaf(ALPHA_F, h2v.x, acc[4]),
                                       fmaf(ALPHA_F, h2v.y, acc[5]));
        __half2 q3 = __floats2half2_rn(fmaf(ALPHA_F, h3v.x, acc[6]),
                                       fmaf(ALPHA_F, h3v.y, acc[7]));
        uint4 ov;
        ov.x = *(unsigned*)&q0;
        ov.y = *(unsigned*)&q1;
        ov.z = *(unsigned*)&q2;
        ov.w = *(unsigned*)&q3;
        ((uint4*)out16)[node * 16 + l16] = ov;
    }
}

// ---------------- launch --------------------------------------------------------
extern "C" void kernel_launch(void* const* d_in, const int* in_sizes, int n_in,
                              void* d_out, int out_size)
{
    const float* x     = (const float*)d_in[0];
    const int*   ei    = (const int*)  d_in[1];
    const float* W_in  = (const float*)d_in[2];
    const float* b_in  = (const float*)d_in[3];
    const float* W1    = (const float*)d_in[4];
    const float* b1    = (const float*)d_in[5];
    const float* g1    = (const float*)d_in[6];
    const float* be1   = (const float*)d_in[7];
    const float* W2    = (const float*)d_in[8];
    const float* b2    = (const float*)d_in[9];
    const float* g2    = (const float*)d_in[10];
    const float* be2   = (const float*)d_in[11];
    const float* W_out = (const float*)d_in[12];
    const float* b_out = (const float*)d_in[13];
    float* out = (float*)d_out;

    int E = in_sizes[1] / 2;
    if (E > EMAX) E = EMAX;
    const int* src = ei;
    const int* dst = ei + E;

    float *h1, *h2, *h0, *dis;
    __half *h016, *cA, *cB;
    int *cnt, *fill, *rowptr, *bsum;
    int2 *csr;
    cudaGetSymbolAddress((void**)&h1,     g_h1);
    cudaGetSymbolAddress((void**)&h2,     g_h2);
    cudaGetSymbolAddress((void**)&h0,     g_h0);
    cudaGetSymbolAddress((void**)&h016,   g_h016);
    cudaGetSymbolAddress((void**)&cA,     g_cA);
    cudaGetSymbolAddress((void**)&cB,     g_cB);
    cudaGetSymbolAddress((void**)&dis,    g_dis);
    cudaGetSymbolAddress((void**)&cnt,    g_cnt);
    cudaGetSymbolAddress((void**)&fill,   g_fill);
    cudaGetSymbolAddress((void**)&rowptr, g_rowptr);
    cudaGetSymbolAddress((void**)&csr,    g_csr);
    cudaGetSymbolAddress((void**)&bsum,   g_bsum);

    const int mt = (NN + 127) / 128;
    const int nb = (NN + 255) / 256;
    const int ne = (E + 255) / 256;

    // ---- MLP: split-bf16 tensor-core GEMMs ----
    wgemm_bias<<<dim3(HID / 128, mt), 256>>>(x,  W_in,  b_in,  h1, NN, INC, HID);
    wgemm_bias<<<dim3(HID / 128, mt), 256>>>(h1, W1,    b1,    h2, NN, HID, HID);
    ln_relu_kernel<<<(NN * 32 + 255) / 256, 256>>>(h2, g1, be1, NN);
    wgemm_bias<<<dim3(HID / 128, mt), 256>>>(h2, W2,    b2,    h1, NN, HID, HID);
    ln_relu_kernel<<<(NN * 32 + 255) / 256, 256>>>(h1, g2, be2, NN);
    wgemm_bias<<<dim3(OUTC / 128, mt), 256>>>(h1, W_out, b_out, h0, NN, HID, OUTC);

    // ---- graph prep (independent of MLP; recomputed every call) ----
    zero_kernel<<<nb, 256>>>(cnt, fill);
    deg_count_kernel<<<ne, 256>>>(dst, cnt, E);
    dis_kernel<<<nb, 256>>>(cnt, dis);
    scan_partial<<<nb, 256>>>(cnt, rowptr, bsum);
    scan_bsums<<<1, 512>>>(bsum, nb);
    add_offsets<<<nb, 256>>>(rowptr, bsum, E);
    fill_kernel<<<ne, 256>>>(src, dst, dis, rowptr, fill, csr, E);

    // fp16 copy of h0 = initial carry and teleport source for steps 0..8
    const int cvt_blocks = (NN * 32 + 255) / 256;
    f2h_kernel<<<cvt_blocks, 256>>>(h0, h016);

    // ---- APPNP: 10 fused pull steps, fp16 carry (2 nodes/warp), fp32 final ----
    const __half* carry = h016;
    const int warps = (NN + 1) / 2;
    const int step_blocks = (warps * 32 + 255) / 256;
    for (int t = 0; t < KSTEPS; t++) {
        int is_last = (t == KSTEPS - 1);
        __half* o16 = (t & 1) ? cB : cA;
        appnp_step_kernel<<<step_blocks, 256>>>(rowptr, csr, dis, h0, h016,
                                                carry, o16, out, is_last);
        carry = o16;
    }
}